// round 5
// baseline (speedup 1.0000x reference)
#include <cuda_runtime.h>
#include <cstdint>

// Problem constants (fixed shapes)
#define NE 8
#define DD 1024
#define HH 4096
#define NTOK 16384
#define BM 128
#define MAX_TILES 136               // ceil(16384/128) + 8 (per-expert pad)
#define PERM_SZ (MAX_TILES * BM)    // 17408

// ---------------- device scratch (static: allocation-free) ----------------
__device__ int   g_expert[NTOK];
__device__ int   g_counts[NE];
__device__ int   g_cursor[NE];
__device__ int   g_aligned_off[NE + 1];
__device__ int   g_perm[PERM_SZ];
__device__ int   g_tile_expert[MAX_TILES];
__device__ float g_zpart[128 * DD];
__device__ float g_ctot[DD];
__device__ float g_scratch[(size_t)PERM_SZ * HH];   // padded rows stay 0 (never written)

// ---------------- helpers ----------------
__device__ __forceinline__ float f_tf32(float x) {
    uint32_t r;
    asm("cvt.rna.tf32.f32 %0, %1;" : "=r"(r) : "f"(x));
    return __uint_as_float(r);
}

// ---------------- K0: zero counts ----------------
__global__ void k_init() {
    if (threadIdx.x < NE) g_counts[threadIdx.x] = 0;
}

// ---------------- K1: router (argmax of x@Wr + br) ----------------
__global__ void k_router(const float* __restrict__ x,
                         const float* __restrict__ Wr,
                         const float* __restrict__ br) {
    __shared__ float sW[NE * DD];   // transposed: sW[e*1024 + d]
    const int tid = threadIdx.x;
    for (int i = tid; i < NE * DD; i += 256) {
        int d = i >> 3, e = i & 7;
        sW[e * DD + d] = Wr[i];
    }
    __syncthreads();

    const int warp = tid >> 5, lane = tid & 31;
    const int t = blockIdx.x * 8 + warp;   // grid = NTOK/8

    float acc[NE];
#pragma unroll
    for (int e = 0; e < NE; e++) acc[e] = 0.f;

    const float* xr = x + (size_t)t * DD;
    for (int d = lane; d < DD; d += 32) {
        float xv = xr[d];
#pragma unroll
        for (int e = 0; e < NE; e++) acc[e] += xv * sW[e * DD + d];
    }
#pragma unroll
    for (int e = 0; e < NE; e++) {
        float v = acc[e];
#pragma unroll
        for (int o = 16; o > 0; o >>= 1) v += __shfl_xor_sync(0xffffffffu, v, o);
        acc[e] = v;
    }
    if (lane == 0) {
        int best = 0;
        float bv = acc[0] + br[0];
#pragma unroll
        for (int e = 1; e < NE; e++) {
            float lv = acc[e] + br[e];
            if (lv > bv) { bv = lv; best = e; }   // first-max wins (jnp.argmax)
        }
        g_expert[t] = best;
        atomicAdd(&g_counts[best], 1);
    }
}

// ---------------- K2: aligned offsets, perm init, tile->expert map ----------------
__global__ void k_setup() {
    const int tid = threadIdx.x;
    if (tid == 0) {
        int off = 0;
        for (int e = 0; e < NE; e++) {
            g_aligned_off[e] = off;
            off += ((g_counts[e] + BM - 1) / BM) * BM;
        }
        g_aligned_off[NE] = off;
    }
    if (tid < NE) g_cursor[tid] = 0;
    __syncthreads();
    for (int i = tid; i < PERM_SZ; i += blockDim.x) g_perm[i] = -1;
    for (int tl = tid; tl < MAX_TILES; tl += blockDim.x) {
        int row = tl * BM, e = -1;
        for (int j = 0; j < NE; j++)
            if (row >= g_aligned_off[j] && row < g_aligned_off[j + 1]) e = j;
        g_tile_expert[tl] = e;
    }
}

// ---------------- K3: scatter token ids into per-expert segments ----------------
__global__ void k_scatter() {
    int t = blockIdx.x * 256 + threadIdx.x;
    int e = g_expert[t];
    int pos = atomicAdd(&g_cursor[e], 1);
    g_perm[g_aligned_off[e] + pos] = t;
}

// ---------------- K4a: partials of z = relu(b1_e) @ W2_e ----------------
__global__ void k_zpart(const float* __restrict__ b1, const float* __restrict__ W2) {
    const int e = blockIdx.x >> 4;       // 8 experts
    const int hc = blockIdx.x & 15;      // 16 chunks of 256 rows
    const int tid = threadIdx.x;         // 256
    float p0 = 0.f, p1 = 0.f, p2 = 0.f, p3 = 0.f;
    const float* W2e = W2 + (size_t)e * HH * DD;
    const int h0 = hc * 256;
    for (int h = 0; h < 256; h++) {
        float s = b1[e * HH + h0 + h];
        if (s > 0.f) {
            const float* row = W2e + (size_t)(h0 + h) * DD;
            p0 += s * row[tid];
            p1 += s * row[tid + 256];
            p2 += s * row[tid + 512];
            p3 += s * row[tid + 768];
        }
    }
    float* zp = g_zpart + (size_t)blockIdx.x * DD;
    zp[tid] = p0; zp[tid + 256] = p1; zp[tid + 512] = p2; zp[tid + 768] = p3;
}

// ---------------- K4b: Ctot[d] = sum partials + sum_e b2[e][d] (deterministic) ----------------
__global__ void k_ctot(const float* __restrict__ b2) {
    int d = blockIdx.x * 256 + threadIdx.x;   // grid 4
    float s = 0.f;
    for (int p = 0; p < 128; p++) s += g_zpart[p * DD + d];
#pragma unroll
    for (int e = 0; e < NE; e++) s += b2[e * DD + d];
    g_ctot[d] = s;
}

// ---------------- grouped GEMM (tf32 mma.sync m16n8k8) ----------------
// PASS1: A = x gathered via perm, W = W1_e [K=1024][N=4096], epi: relu(+b1)-relu(b1) -> g_scratch
// PASS2: A = g_scratch rows,     W = W2_e [K=4096][N=1024], epi: +Ctot, scatter to out[token]
template <int KDIM, int NDIM, bool PASS1>
__global__ void __launch_bounds__(256)
k_gemm(const float* __restrict__ A_g, const float* __restrict__ W_g,
       const float* __restrict__ bias_g, float* __restrict__ out_g) {
    const int e = g_tile_expert[blockIdx.x];
    if (e < 0) return;

    __shared__ __align__(16) float As[32][132];
    __shared__ __align__(16) float Bs[32][132];
    __shared__ int   sRow[BM];
    __shared__ float sBias[128];

    const int tid = threadIdx.x;
    const int tile_m = blockIdx.x, tile_n = blockIdx.y;

    if (tid < 128) {
        sRow[tid] = g_perm[tile_m * BM + tid];
        if (PASS1) sBias[tid] = bias_g[(size_t)e * NDIM + tile_n * 128 + tid];
        else       sBias[tid] = g_ctot[tile_n * 128 + tid];
    }
    __syncthreads();

    const float* Asrc = PASS1 ? A_g : &g_scratch[0];
    const float* We = W_g + (size_t)e * KDIM * NDIM + tile_n * 128;

    // ---- global load descriptors ----
    const float* aptr[4];
    int s_am[4], s_ak[4];
    const float* bptr[4];
    int s_bk[4], s_bn[4];
#pragma unroll
    for (int i = 0; i < 4; i++) {
        int idx = tid + i * 256;
        int m = idx >> 3, k4 = idx & 7;
        s_am[i] = m; s_ak[i] = k4 * 4;
        if (PASS1) {
            int tok = sRow[m];
            aptr[i] = (tok >= 0) ? (Asrc + (size_t)tok * KDIM + k4 * 4) : nullptr;
        } else {
            aptr[i] = Asrc + (size_t)(tile_m * BM + m) * KDIM + k4 * 4;
        }
        int bk = idx >> 5, bn4 = idx & 31;
        s_bk[i] = bk; s_bn[i] = bn4 * 4;
        bptr[i] = We + (size_t)bk * NDIM + bn4 * 4;
    }

    const int warp = tid >> 5, lane = tid & 31;
    const int wm = warp >> 1, wn = warp & 1;     // 4x2 warp grid, warp tile 32x64
    const int g = lane >> 2, c = lane & 3;

    float acc[2][8][4];
#pragma unroll
    for (int a = 0; a < 2; a++)
#pragma unroll
        for (int b = 0; b < 8; b++)
#pragma unroll
            for (int q = 0; q < 4; q++) acc[a][b][q] = 0.f;

    float4 pa[4], pb[4];
#define LOAD_GLOBAL(K0)                                                          \
    do {                                                                         \
        _Pragma("unroll")                                                        \
        for (int i = 0; i < 4; i++) {                                            \
            if (PASS1 && aptr[i] == nullptr) pa[i] = make_float4(0.f,0.f,0.f,0.f);\
            else pa[i] = *reinterpret_cast<const float4*>(aptr[i] + (K0));       \
        }                                                                        \
        _Pragma("unroll")                                                        \
        for (int i = 0; i < 4; i++)                                              \
            pb[i] = *reinterpret_cast<const float4*>(bptr[i] + (size_t)(K0) * NDIM); \
    } while (0)

    LOAD_GLOBAL(0);

    for (int k0 = 0; k0 < KDIM; k0 += 32) {
        __syncthreads();
#pragma unroll
        for (int i = 0; i < 4; i++) {
            As[s_ak[i] + 0][s_am[i]] = f_tf32(pa[i].x);
            As[s_ak[i] + 1][s_am[i]] = f_tf32(pa[i].y);
            As[s_ak[i] + 2][s_am[i]] = f_tf32(pa[i].z);
            As[s_ak[i] + 3][s_am[i]] = f_tf32(pa[i].w);
        }
#pragma unroll
        for (int i = 0; i < 4; i++) {
            float4 v;
            v.x = f_tf32(pb[i].x); v.y = f_tf32(pb[i].y);
            v.z = f_tf32(pb[i].z); v.w = f_tf32(pb[i].w);
            *reinterpret_cast<float4*>(&Bs[s_bk[i]][s_bn[i]]) = v;
        }
        __syncthreads();
        if (k0 + 32 < KDIM) LOAD_GLOBAL(k0 + 32);

#pragma unroll
        for (int ks = 0; ks < 4; ks++) {
            const int kb = ks * 8;
            uint32_t af[2][4];
#pragma unroll
            for (int ma = 0; ma < 2; ma++) {
                int mr = wm * 32 + ma * 16 + g;
                af[ma][0] = __float_as_uint(As[kb + c][mr]);
                af[ma][1] = __float_as_uint(As[kb + c][mr + 8]);
                af[ma][2] = __float_as_uint(As[kb + c + 4][mr]);
                af[ma][3] = __float_as_uint(As[kb + c + 4][mr + 8]);
            }
#pragma unroll
            for (int na = 0; na < 8; na++) {
                int col = wn * 64 + na * 8 + g;
                uint32_t b0 = __float_as_uint(Bs[kb + c][col]);
                uint32_t b1r = __float_as_uint(Bs[kb + c + 4][col]);
#pragma unroll
                for (int ma = 0; ma < 2; ma++) {
                    float* d = acc[ma][na];
                    asm volatile(
                        "mma.sync.aligned.m16n8k8.row.col.f32.tf32.tf32.f32 "
                        "{%0,%1,%2,%3},{%4,%5,%6,%7},{%8,%9},{%0,%1,%2,%3};\n"
                        : "+f"(d[0]), "+f"(d[1]), "+f"(d[2]), "+f"(d[3])
                        : "r"(af[ma][0]), "r"(af[ma][1]), "r"(af[ma][2]), "r"(af[ma][3]),
                          "r"(b0), "r"(b1r));
                }
            }
        }
    }
#undef LOAD_GLOBAL

    // ---- epilogue ----
    float* Odst = PASS1 ? &g_scratch[0] : out_g;
#pragma unroll
    for (int ma = 0; ma < 2; ma++) {
#pragma unroll
        for (int half = 0; half < 2; half++) {
            int lr = wm * 32 + ma * 16 + g + half * 8;
            int tok = sRow[lr];
            if (tok < 0) continue;
            int rowp = tile_m * BM + lr;
#pragma unroll
            for (int na = 0; na < 8; na++) {
                int ncl = wn * 64 + na * 8 + c * 2;
                float a0 = acc[ma][na][half * 2 + 0];
                float a1 = acc[ma][na][half * 2 + 1];
                float b0 = sBias[ncl], b1v = sBias[ncl + 1];
                float2 v;
                if (PASS1) {
                    v.x = fmaxf(a0 + b0, 0.f) - fmaxf(b0, 0.f);
                    v.y = fmaxf(a1 + b1v, 0.f) - fmaxf(b1v, 0.f);
                    *reinterpret_cast<float2*>(Odst + (size_t)rowp * NDIM + tile_n * 128 + ncl) = v;
                } else {
                    v.x = a0 + b0;
                    v.y = a1 + b1v;
                    *reinterpret_cast<float2*>(Odst + (size_t)tok * NDIM + tile_n * 128 + ncl) = v;
                }
            }
        }
    }
}

// ---------------- launch ----------------
extern "C" void kernel_launch(void* const* d_in, const int* in_sizes, int n_in,
                              void* d_out, int out_size) {
    const float* x  = (const float*)d_in[0];
    const float* W1 = (const float*)d_in[1];
    const float* b1 = (const float*)d_in[2];
    const float* W2 = (const float*)d_in[3];
    const float* b2 = (const float*)d_in[4];
    const float* Wr = (const float*)d_in[5];
    const float* br = (const float*)d_in[6];
    float* out = (float*)d_out;

    k_init<<<1, 32>>>();
    k_router<<<NTOK / 8, 256>>>(x, Wr, br);
    k_setup<<<1, 256>>>();
    k_scatter<<<NTOK / 256, 256>>>();
    k_zpart<<<128, 256>>>(b1, W2);
    k_ctot<<<4, 256>>>(b2);

    dim3 g1(MAX_TILES, HH / 128);   // 136 x 32
    k_gemm<DD, HH, true><<<g1, 256>>>(x, W1, b1, nullptr);

    dim3 g2(MAX_TILES, DD / 128);   // 136 x 8
    k_gemm<HH, DD, false><<<g2, 256>>>(nullptr, W2, nullptr, out);
}

// round 7
// speedup vs baseline: 1.5782x; 1.5782x over previous
#include <cuda_runtime.h>
#include <cstdint>

// ---------------- problem constants ----------------
#define NE 8
#define DD 1024
#define HH 4096
#define NTOK 16384
#define BM 128
#define BK 32
#define MAX_TILES 136               // ceil(16384/128) + 8 pad tiles
#define PERM_SZ (MAX_TILES * BM)    // 17408

// ---------------- GEMM smem geometry ----------------
#define A_STRIDE 36                 // floats per A row (128B data + pad) -> banks 4g+c, conflict-free
#define B_STRIDE 136                // floats per B row -> banks 8c+g, conflict-free
#define A_FLOATS (BM * A_STRIDE)    // 4608
#define B_FLOATS (BK * B_STRIDE)    // 4352
#define STAGE_FLOATS (A_FLOATS + B_FLOATS)   // 8960
#define NSTAGE 3
#define SMEM_BYTES (1024 + NSTAGE * STAGE_FLOATS * 4)   // 108544

// ---------------- device scratch (static: allocation-free) ----------------
__device__ int   g_expert[NTOK];
__device__ int   g_counts[NE];
__device__ int   g_cursor[NE];
__device__ int   g_aligned_off[NE + 1];
__device__ int   g_perm[PERM_SZ];
__device__ int   g_tile_expert[MAX_TILES];
__device__ float g_zpart[128 * DD];
__device__ float g_ctot[DD];
__device__ float g_scratch[(size_t)PERM_SZ * HH];   // zero-init; pad rows stay 0 forever

// ---------------- helpers ----------------
__device__ __forceinline__ float f_tf32(float x) {
    uint32_t r;
    asm("cvt.rna.tf32.f32 %0, %1;" : "=r"(r) : "f"(x));
    return __uint_as_float(r);
}
__device__ __forceinline__ uint32_t smem_u32(const void* p) {
    uint32_t a;
    asm("{ .reg .u64 t; cvta.to.shared.u64 t, %1; cvt.u32.u64 %0, t; }" : "=r"(a) : "l"(p));
    return a;
}
__device__ __forceinline__ void cp16(uint32_t dst, const void* src, uint32_t srcsz) {
    asm volatile("cp.async.cg.shared.global [%0], [%1], 16, %2;"
                 :: "r"(dst), "l"(src), "r"(srcsz) : "memory");
}

// ---------------- K0: zero counts ----------------
__global__ void k_init() {
    if (threadIdx.x < NE) g_counts[threadIdx.x] = 0;
}

// ---------------- K1: router (argmax of x@Wr + br) ----------------
__global__ void k_router(const float* __restrict__ x,
                         const float* __restrict__ Wr,
                         const float* __restrict__ br) {
    __shared__ float sW[NE * DD];   // transposed: sW[e*1024 + d]
    const int tid = threadIdx.x;
    for (int i = tid; i < NE * DD; i += 256) {
        int d = i >> 3, e = i & 7;
        sW[e * DD + d] = Wr[i];
    }
    __syncthreads();

    const int warp = tid >> 5, lane = tid & 31;
    const int t = blockIdx.x * 8 + warp;   // grid = NTOK/8

    float acc[NE];
#pragma unroll
    for (int e = 0; e < NE; e++) acc[e] = 0.f;

    const float* xr = x + (size_t)t * DD;
    for (int d = lane; d < DD; d += 32) {
        float xv = xr[d];
#pragma unroll
        for (int e = 0; e < NE; e++) acc[e] += xv * sW[e * DD + d];
    }
#pragma unroll
    for (int e = 0; e < NE; e++) {
        float v = acc[e];
#pragma unroll
        for (int o = 16; o > 0; o >>= 1) v += __shfl_xor_sync(0xffffffffu, v, o);
        acc[e] = v;
    }
    if (lane == 0) {
        int best = 0;
        float bv = acc[0] + br[0];
#pragma unroll
        for (int e = 1; e < NE; e++) {
            float lv = acc[e] + br[e];
            if (lv > bv) { bv = lv; best = e; }   // first-max wins (jnp.argmax)
        }
        g_expert[t] = best;
        atomicAdd(&g_counts[best], 1);
    }
}

// ---------------- K2: aligned offsets, perm init, tile->expert map ----------------
__global__ void k_setup() {
    const int tid = threadIdx.x;
    if (tid == 0) {
        int off = 0;
        for (int e = 0; e < NE; e++) {
            g_aligned_off[e] = off;
            off += ((g_counts[e] + BM - 1) / BM) * BM;
        }
        g_aligned_off[NE] = off;
    }
    if (tid < NE) g_cursor[tid] = 0;
    __syncthreads();
    for (int i = tid; i < PERM_SZ; i += blockDim.x) g_perm[i] = -1;
    for (int tl = tid; tl < MAX_TILES; tl += blockDim.x) {
        int row = tl * BM, e = -1;
        for (int j = 0; j < NE; j++)
            if (row >= g_aligned_off[j] && row < g_aligned_off[j + 1]) e = j;
        g_tile_expert[tl] = e;
    }
}

// ---------------- K3: scatter token ids into per-expert segments ----------------
__global__ void k_scatter() {
    int t = blockIdx.x * 256 + threadIdx.x;
    int e = g_expert[t];
    int pos = atomicAdd(&g_cursor[e], 1);
    g_perm[g_aligned_off[e] + pos] = t;
}

// ---------------- K4a: partials of z = relu(b1_e) @ W2_e ----------------
__global__ void k_zpart(const float* __restrict__ b1, const float* __restrict__ W2) {
    const int e = blockIdx.x >> 4;       // 8 experts
    const int hc = blockIdx.x & 15;      // 16 chunks of 256 rows
    const int tid = threadIdx.x;         // 256
    float p0 = 0.f, p1 = 0.f, p2 = 0.f, p3 = 0.f;
    const float* W2e = W2 + (size_t)e * HH * DD;
    const int h0 = hc * 256;
    for (int h = 0; h < 256; h++) {
        float s = b1[e * HH + h0 + h];
        if (s > 0.f) {
            const float* row = W2e + (size_t)(h0 + h) * DD;
            p0 += s * row[tid];
            p1 += s * row[tid + 256];
            p2 += s * row[tid + 512];
            p3 += s * row[tid + 768];
        }
    }
    float* zp = g_zpart + (size_t)blockIdx.x * DD;
    zp[tid] = p0; zp[tid + 256] = p1; zp[tid + 512] = p2; zp[tid + 768] = p3;
}

// ---------------- K4b: Ctot (deterministic reduction) ----------------
__global__ void k_ctot(const float* __restrict__ b2) {
    int d = blockIdx.x * 256 + threadIdx.x;   // grid 4
    float s = 0.f;
    for (int p = 0; p < 128; p++) s += g_zpart[p * DD + d];
#pragma unroll
    for (int e = 0; e < NE; e++) s += b2[e * DD + d];
    g_ctot[d] = s;
}

// ---------------- grouped GEMM (tf32 mma.sync, cp.async 3-stage pipeline) ----------------
// PASS1: A = x gathered via perm, W = W1_e [K=1024][N=4096], epi: relu(+b1)-relu(b1) -> g_scratch
// PASS2: A = g_scratch rows,     W = W2_e [K=4096][N=1024], epi: +Ctot, scatter to out[token]
template <int KDIM, int NDIM, bool PASS1>
__global__ void __launch_bounds__(256, 1)
k_gemm(const float* __restrict__ A_g, const float* __restrict__ W_g,
       const float* __restrict__ bias_g, float* __restrict__ out_g) {
    extern __shared__ float smem[];
    const int tile_n = blockIdx.x, tile_m = blockIdx.y;
    const int e = g_tile_expert[tile_m];
    if (e < 0) return;

    int*   sRow  = (int*)smem;        // 128 ints
    float* sBias = smem + 128;        // 128 floats
    float* sStage = smem + 256;       // 3 stages of A|B

    const int tid = threadIdx.x;
    if (tid < 128) {
        sRow[tid] = g_perm[tile_m * BM + tid];
        sBias[tid] = PASS1 ? bias_g[(size_t)e * NDIM + tile_n * 128 + tid]
                           : g_ctot[tile_n * 128 + tid];
    }
    __syncthreads();

    // ---- producer descriptors (each thread moves 4x16B of A and 4x16B of B per chunk) ----
    const int ak4 = tid & 7;              // 16B column within a 128B A-row chunk
    const float* aptr[4];
    uint32_t dA[4], asz[4];
#pragma unroll
    for (int i = 0; i < 4; i++) {
        int m = (tid >> 3) + i * 32;      // 0..127
        dA[i] = (uint32_t)(m * A_STRIDE + ak4 * 4) * 4;
        if (PASS1) {
            int tok = sRow[m];
            asz[i] = (tok >= 0) ? 16u : 0u;          // src-size 0 -> HW zero-fill
            aptr[i] = A_g + (size_t)(tok >= 0 ? tok : 0) * KDIM + ak4 * 4;
        } else {
            asz[i] = 16u;
            aptr[i] = &g_scratch[0] + (size_t)(tile_m * BM + m) * KDIM + ak4 * 4;
        }
    }
    const int bn4 = tid & 31;             // 16B column within a 512B B-row
    const float* bptr[4];
    uint32_t dB[4];
    const float* We = W_g + (size_t)e * KDIM * NDIM + (size_t)tile_n * 128;
#pragma unroll
    for (int i = 0; i < 4; i++) {
        int bk = (tid >> 5) + i * 8;      // 0..31
        dB[i] = (uint32_t)(A_FLOATS + bk * B_STRIDE + bn4 * 4) * 4;
        bptr[i] = We + (size_t)bk * NDIM + bn4 * 4;
    }

    auto issue = [&](int cc, int s) {
        uint32_t base = smem_u32(sStage + (size_t)s * STAGE_FLOATS);
#pragma unroll
        for (int i = 0; i < 4; i++)
            cp16(base + dA[i], aptr[i] + (size_t)cc * BK, asz[i]);
#pragma unroll
        for (int i = 0; i < 4; i++)
            cp16(base + dB[i], bptr[i] + (size_t)cc * BK * NDIM, 16u);
        asm volatile("cp.async.commit_group;" ::: "memory");
    };

    constexpr int NCHUNK = KDIM / BK;
    issue(0, 0); issue(1, 1); issue(2, 2);

    const int warp = tid >> 5, lane = tid & 31;
    const int wm = warp >> 1, wn = warp & 1;   // 4x2 warp grid, warp tile 32x64
    const int g = lane >> 2, c = lane & 3;

    float acc[2][8][4];
#pragma unroll
    for (int a = 0; a < 2; a++)
#pragma unroll
        for (int b = 0; b < 8; b++)
#pragma unroll
            for (int q = 0; q < 4; q++) acc[a][b][q] = 0.f;

    for (int ch = 0; ch < NCHUNK; ++ch) {
        asm volatile("cp.async.wait_group 2;" ::: "memory");
        __syncthreads();
        const float* As_ = sStage + (size_t)(ch % 3) * STAGE_FLOATS;
        const float* Bs_ = As_ + A_FLOATS;

#pragma unroll
        for (int ks = 0; ks < 4; ++ks) {
            const int kb = ks * 8;
            uint32_t af[2][4];
#pragma unroll
            for (int ma = 0; ma < 2; ++ma) {
                const float* ar = As_ + (wm * 32 + ma * 16 + g) * A_STRIDE + kb + c;
                af[ma][0] = __float_as_uint(f_tf32(ar[0]));
                af[ma][1] = __float_as_uint(f_tf32(ar[8 * A_STRIDE]));
                af[ma][2] = __float_as_uint(f_tf32(ar[4]));
                af[ma][3] = __float_as_uint(f_tf32(ar[8 * A_STRIDE + 4]));
            }
#pragma unroll
            for (int na = 0; na < 8; ++na) {
                const float* bc = Bs_ + (kb + c) * B_STRIDE + wn * 64 + na * 8 + g;
                uint32_t b0 = __float_as_uint(f_tf32(bc[0]));
                uint32_t b1r = __float_as_uint(f_tf32(bc[4 * B_STRIDE]));
#pragma unroll
                for (int ma = 0; ma < 2; ++ma) {
                    float* d = acc[ma][na];
                    asm volatile(
                        "mma.sync.aligned.m16n8k8.row.col.f32.tf32.tf32.f32 "
                        "{%0,%1,%2,%3},{%4,%5,%6,%7},{%8,%9},{%0,%1,%2,%3};\n"
                        : "+f"(d[0]), "+f"(d[1]), "+f"(d[2]), "+f"(d[3])
                        : "r"(af[ma][0]), "r"(af[ma][1]), "r"(af[ma][2]), "r"(af[ma][3]),
                          "r"(b0), "r"(b1r));
                }
            }
        }
        __syncthreads();
        if (ch + 3 < NCHUNK) issue(ch + 3, ch % 3);
    }

    // ---- epilogue ----
    float* Odst = PASS1 ? &g_scratch[0] : out_g;
#pragma unroll
    for (int ma = 0; ma < 2; ma++) {
#pragma unroll
        for (int half = 0; half < 2; half++) {
            int lr = wm * 32 + ma * 16 + g + half * 8;
            int tok = sRow[lr];
            if (tok < 0) continue;
            int rowp = tile_m * BM + lr;
#pragma unroll
            for (int na = 0; na < 8; na++) {
                int ncl = wn * 64 + na * 8 + c * 2;
                float a0 = acc[ma][na][half * 2 + 0];
                float a1 = acc[ma][na][half * 2 + 1];
                float b0 = sBias[ncl], b1v = sBias[ncl + 1];
                float2 v;
                if (PASS1) {
                    v.x = fmaxf(a0 + b0, 0.f) - fmaxf(b0, 0.f);
                    v.y = fmaxf(a1 + b1v, 0.f) - fmaxf(b1v, 0.f);
                    *reinterpret_cast<float2*>(Odst + (size_t)rowp * NDIM + tile_n * 128 + ncl) = v;
                } else {
                    v.x = a0 + b0;
                    v.y = a1 + b1v;
                    *reinterpret_cast<float2*>(Odst + (size_t)tok * NDIM + tile_n * 128 + ncl) = v;
                }
            }
        }
    }
}

// ---------------- launch ----------------
extern "C" void kernel_launch(void* const* d_in, const int* in_sizes, int n_in,
                              void* d_out, int out_size) {
    const float* x  = (const float*)d_in[0];
    const float* W1 = (const float*)d_in[1];
    const float* b1 = (const float*)d_in[2];
    const float* W2 = (const float*)d_in[3];
    const float* b2 = (const float*)d_in[4];
    const float* Wr = (const float*)d_in[5];
    const float* br = (const float*)d_in[6];
    float* out = (float*)d_out;

    cudaFuncSetAttribute(k_gemm<DD, HH, true>,
                         cudaFuncAttributeMaxDynamicSharedMemorySize, SMEM_BYTES);
    cudaFuncSetAttribute(k_gemm<HH, DD, false>,
                         cudaFuncAttributeMaxDynamicSharedMemorySize, SMEM_BYTES);

    k_init<<<1, 32>>>();
    k_router<<<NTOK / 8, 256>>>(x, Wr, br);
    k_setup<<<1, 256>>>();
    k_scatter<<<NTOK / 256, 256>>>();
    k_zpart<<<128, 256>>>(b1, W2);
    k_ctot<<<4, 256>>>(b2);

    dim3 g1(HH / 128, MAX_TILES);   // 32 x 136
    k_gemm<DD, HH, true><<<g1, 256, SMEM_BYTES>>>(x, W1, b1, nullptr);

    dim3 g2(DD / 128, MAX_TILES);   // 8 x 136
    k_gemm<HH, DD, false><<<g2, 256, SMEM_BYTES>>>(nullptr, W2, nullptr, out);
}